// round 11
// baseline (speedup 1.0000x reference)
#include <cuda_runtime.h>
#include <cuda_fp16.h>
#include <math.h>
#include <stdint.h>

#define N_ROWS 32768
#define D_IN   3000
#define KPAD1  3072
#define H0     1024
#define H1     256
#define K_CL   20

// ---------------- scratch (static device arrays; no allocs) ----------------
__device__ __align__(16) __half g_w1t[(size_t)H0 * KPAD1];
__device__ __align__(16) __half g_hh[(size_t)N_ROWS * H0];
__device__ __align__(16) __half g_w2t[(size_t)H1 * H0];

// ---------------- helpers ----------------
__device__ __forceinline__ uint32_t smem_u32(const void* p) {
    uint32_t a;
    asm("{ .reg .u64 t; cvta.to.shared.u64 t, %1; cvt.u32.u64 %0, t; }" : "=r"(a) : "l"(p));
    return a;
}
__device__ __forceinline__ void cp_async16(uint32_t s, const void* g) {
    asm volatile("cp.async.cg.shared.global [%0], [%1], 16;" :: "r"(s), "l"(g));
}
__device__ __forceinline__ void ldm_x4(uint32_t* r, uint32_t addr) {
    asm volatile("ldmatrix.sync.aligned.m8n8.x4.shared.b16 {%0,%1,%2,%3}, [%4];"
        : "=r"(r[0]), "=r"(r[1]), "=r"(r[2]), "=r"(r[3]) : "r"(addr));
}
__device__ __forceinline__ void mma_f16(float* c, const uint32_t* a, const uint32_t* b) {
    asm volatile(
        "mma.sync.aligned.m16n8k16.row.col.f32.f16.f16.f32 "
        "{%0,%1,%2,%3}, {%4,%5,%6,%7}, {%8,%9}, {%0,%1,%2,%3};"
        : "+f"(c[0]), "+f"(c[1]), "+f"(c[2]), "+f"(c[3])
        : "r"(a[0]), "r"(a[1]), "r"(a[2]), "r"(a[3]), "r"(b[0]), "r"(b[1]));
}

// ---- mbarrier (sm_80/sm_90 base PTX; legal on compute_103) ----
#define MBAR_INIT(a, c) \
    asm volatile("mbarrier.init.shared.b64 [%0], %1;" :: "r"(a), "r"(c) : "memory")
#define MBAR_ARRIVE(a) \
    asm volatile("mbarrier.arrive.release.cta.shared.b64 _, [%0];" :: "r"(a) : "memory")
#define CP_ASYNC_MBAR_ARRIVE(a) \
    asm volatile("cp.async.mbarrier.arrive.noinc.shared.b64 [%0];" :: "r"(a) : "memory")

__device__ __forceinline__ void mbar_wait_acq(uint32_t mbar, uint32_t parity) {
    uint32_t done;
    asm volatile(
        "{\n\t.reg .pred p;\n\t"
        "mbarrier.try_wait.parity.acquire.cta.shared::cta.b64 p, [%1], %2;\n\t"
        "selp.b32 %0, 1, 0, p;\n\t}"
        : "=r"(done) : "r"(mbar), "r"(parity) : "memory");
    if (!done) {
        asm volatile(
            "{\n\t.reg .pred P1;\n\t"
            "WL_%=:\n\t"
            "mbarrier.try_wait.parity.acquire.cta.shared::cta.b64 P1, [%0], %1, 0x989680;\n\t"
            "@P1 bra.uni WD_%=;\n\t"
            "bra.uni WL_%=;\n\t"
            "WD_%=:\n\t}"
            :: "r"(mbar), "r"(parity) : "memory");
    }
}
__device__ __forceinline__ void mbar_wait_relaxed(uint32_t mbar, uint32_t parity) {
    uint32_t done;
    asm volatile(
        "{\n\t.reg .pred p;\n\t"
        "mbarrier.try_wait.parity.relaxed.cta.shared::cta.b64 p, [%1], %2, 0x989680;\n\t"
        "selp.b32 %0, 1, 0, p;\n\t}"
        : "=r"(done) : "r"(mbar), "r"(parity) : "memory");
    if (!done) {
        asm volatile(
            "{\n\t.reg .pred P1;\n\t"
            "WL_%=:\n\t"
            "mbarrier.try_wait.parity.relaxed.cta.shared::cta.b64 P1, [%0], %1, 0x989680;\n\t"
            "@P1 bra.uni WD_%=;\n\t"
            "bra.uni WL_%=;\n\t"
            "WD_%=:\n\t}"
            :: "r"(mbar), "r"(parity) : "memory");
    }
}

// ---------------- preprocess: W [K, N] fp32 -> Wt [N, Kpad] fp16 ----------------
__global__ __launch_bounds__(256)
void transpose_kernel(const float* __restrict__ W,
                      __half* __restrict__ T,
                      int K, int N, int Kpad)
{
    __shared__ float s[32][33];
    const int k0 = blockIdx.x * 32;
    const int n0 = blockIdx.y * 32;
    const int tx = threadIdx.x, ty = threadIdx.y;
    #pragma unroll
    for (int j = 0; j < 32; j += 8) {
        int k = k0 + ty + j;
        s[ty + j][tx] = (k < K) ? W[(size_t)k * N + n0 + tx] : 0.0f;
    }
    __syncthreads();
    #pragma unroll
    for (int j = 0; j < 32; j += 8) {
        int n = n0 + ty + j;
        int kk = k0 + tx;
        T[(size_t)n * Kpad + kk] = __float2half_rn(s[tx][ty + j]);
    }
}

// ---------------- warp-specialized HMMA fp16 GEMM ----------------
// 8 consumer warps: CTA tile 128x128, warp tile 64x32, K-chunk 64 fp16.
// 2 producer warps: A loaded fp32->fp16 converted in-flight (AFP32) or cp.async;
// B always cp.async. 3 stages x 32KB, mbarrier rings, no mainloop __syncthreads.
#define TILE_A   16384
#define STAGE_B  32768
#define NSTAGE   3
#define MBAR_OFF (NSTAGE * STAGE_B)           // 98304
#define GEMM_SMEM (MBAR_OFF + 64)

// EPI=0: bias+SiLU -> fp16.  EPI=1: bias -> fp32.
// AFP32: A is fp32 with row stride ldA and valid cols kValid (zero-pad beyond).
template <int EPI, bool AFP32>
__global__ __launch_bounds__(320, 2)
void gemm_mma_kernel(const void* __restrict__ Av,
                     const __half* __restrict__ B,
                     const float* __restrict__ bias,
                     __half* __restrict__ OutH,
                     float* __restrict__ OutF,
                     int ldA, int Kpad, int kValid, int NC, int ldOut)
{
    extern __shared__ char smem[];
    const uint32_t sbase = smem_u32(smem);
    const int tid  = threadIdx.x;
    const int wid  = tid >> 5;
    const int lane = tid & 31;
    const int mBase = blockIdx.y * 128;
    const int nBase = blockIdx.x * 128;

    // mbarriers: full[s] = MBAR_OFF + s*8, empty[s] = MBAR_OFF+24 + s*8
    if (tid == 0) {
        #pragma unroll
        for (int s = 0; s < NSTAGE; s++) {
            MBAR_INIT(sbase + MBAR_OFF + s * 8, AFP32 ? 128 : 64);
            MBAR_INIT(sbase + MBAR_OFF + 24 + s * 8, 256);
        }
    }
    __syncthreads();

    if (wid >= 8) {
        // ================= producer warps (wid 8,9) =================
        const int pt = (wid - 8) * 32 + lane;    // 0..63
        const int c  = pt & 7;                    // 16B (8-element) column
        const int r0 = pt >> 3;                   // 0..7 (rows r0+8j)
        // swizzled smem unit offset: row&7 == r0 for all j -> xor constant
        const uint32_t swu = (uint32_t)(r0 * 128 + ((c * 16) ^ (r0 << 4)));

        const float*  gAf = (const float*)Av  + (size_t)(mBase + r0) * ldA + c * 8;
        const __half* gAh = (const __half*)Av + (size_t)(mBase + r0) * ldA + c * 8;
        const __half* gBh = B + (size_t)(nBase + r0) * Kpad + c * 8;

        int ps = 0, pph = 1;
        int col0 = c * 8;
        for (int ck = 0; ck < NC; ck++) {
            mbar_wait_relaxed(sbase + MBAR_OFF + 24 + ps * 8, pph);
            const uint32_t st = sbase + ps * STAGE_B;
            const uint32_t mbF = sbase + MBAR_OFF + ps * 8;

            // B tile: 16 units via cp.async
            #pragma unroll
            for (int j = 0; j < 16; j++)
                cp_async16(st + TILE_A + swu + j * 1024, gBh + (size_t)j * 8 * Kpad);

            if (AFP32) {
                const bool p0 = (col0 < kValid);
                const bool p1 = (col0 + 4 < kValid);
                #pragma unroll 4
                for (int j = 0; j < 16; j++) {
                    const float* s4 = gAf + (size_t)j * 8 * ldA;
                    float4 fa = p0 ? *reinterpret_cast<const float4*>(s4)
                                   : make_float4(0.f, 0.f, 0.f, 0.f);
                    float4 fb = p1 ? *reinterpret_cast<const float4*>(s4 + 4)
                                   : make_float4(0.f, 0.f, 0.f, 0.f);
                    __half2 h0 = __floats2half2_rn(fa.x, fa.y);
                    __half2 h1 = __floats2half2_rn(fa.z, fa.w);
                    __half2 h2 = __floats2half2_rn(fb.x, fb.y);
                    __half2 h3 = __floats2half2_rn(fb.z, fb.w);
                    uint4 v;
                    v.x = *reinterpret_cast<uint32_t*>(&h0);
                    v.y = *reinterpret_cast<uint32_t*>(&h1);
                    v.z = *reinterpret_cast<uint32_t*>(&h2);
                    v.w = *reinterpret_cast<uint32_t*>(&h3);
                    uint32_t sa = st + swu + j * 1024;
                    asm volatile("st.shared.v4.b32 [%0], {%1,%2,%3,%4};"
                        :: "r"(sa), "r"(v.x), "r"(v.y), "r"(v.z), "r"(v.w) : "memory");
                }
                MBAR_ARRIVE(mbF);          // A stores visible (release)
            } else {
                #pragma unroll
                for (int j = 0; j < 16; j++)
                    cp_async16(st + swu + j * 1024, gAh + (size_t)j * 8 * Kpad);
            }
            CP_ASYNC_MBAR_ARRIVE(mbF);     // B (and fp16-A) copies complete

            gAf += 64; gAh += 64; gBh += 64; col0 += 64;
            if (++ps == NSTAGE) { ps = 0; pph ^= 1; }
        }
        return;
    }

    // ================= consumer warps (0..7) =================
    const int warpM = (wid & 1) * 64;    // 0 / 64
    const int warpN = (wid >> 1) * 32;   // 0..96

    const int aRowIn = lane & 15;
    const int kHalf  = (lane >> 4) << 4;
    uint32_t offA0[4], offB0[2];
    #pragma unroll
    for (int mt = 0; mt < 4; mt++) {
        int row = warpM + mt * 16 + aRowIn;
        offA0[mt] = (uint32_t)(row * 128 + (kHalf ^ ((row & 7) << 4)));
    }
    #pragma unroll
    for (int nt2 = 0; nt2 < 2; nt2++) {
        int row = warpN + nt2 * 16 + aRowIn;
        offB0[nt2] = (uint32_t)(row * 128 + (kHalf ^ ((row & 7) << 4)));
    }

    float acc[4][4][4];
    #pragma unroll
    for (int i = 0; i < 4; i++)
        #pragma unroll
        for (int j = 0; j < 4; j++)
            #pragma unroll
            for (int k = 0; k < 4; k++)
                acc[i][j][k] = 0.0f;

    int cs = 0, cph = 0;
    for (int ck = 0; ck < NC; ck++) {
        mbar_wait_acq(sbase + MBAR_OFF + cs * 8, cph);
        const uint32_t st = sbase + cs * STAGE_B;

        #pragma unroll
        for (int ks = 0; ks < 4; ks++) {
            const uint32_t kx = ks * 32;
            uint32_t fa[4][4], fb[4][2];
            #pragma unroll
            for (int mt = 0; mt < 4; mt++)
                ldm_x4(fa[mt], (st + offA0[mt]) ^ kx);
            #pragma unroll
            for (int nt2 = 0; nt2 < 2; nt2++) {
                uint32_t r[4];
                ldm_x4(r, (st + TILE_A + offB0[nt2]) ^ kx);
                fb[nt2 * 2][0] = r[0]; fb[nt2 * 2][1] = r[2];
                fb[nt2 * 2 + 1][0] = r[1]; fb[nt2 * 2 + 1][1] = r[3];
            }
            #pragma unroll
            for (int mt = 0; mt < 4; mt++)
                #pragma unroll
                for (int nt = 0; nt < 4; nt++)
                    mma_f16(acc[mt][nt], fa[mt], fb[nt]);
        }

        MBAR_ARRIVE(sbase + MBAR_OFF + 24 + cs * 8);
        if (++cs == NSTAGE) { cs = 0; cph ^= 1; }
    }

    // ---- epilogue ----
    const int rBase = mBase + warpM + (lane >> 2);
    const int cBase = nBase + warpN + (lane & 3) * 2;

    #pragma unroll
    for (int mt = 0; mt < 4; mt++) {
        #pragma unroll
        for (int nt = 0; nt < 4; nt++) {
            const int col = cBase + nt * 8;
            const float b0 = bias[col];
            const float b1 = bias[col + 1];
            #pragma unroll
            for (int h = 0; h < 2; h++) {
                const int row = rBase + mt * 16 + h * 8;
                float v0 = acc[mt][nt][2 * h]     + b0;
                float v1 = acc[mt][nt][2 * h + 1] + b1;
                if (EPI == 0) {
                    v0 = v0 / (1.0f + expf(-v0));
                    v1 = v1 / (1.0f + expf(-v1));
                    *reinterpret_cast<__half2*>(OutH + (size_t)row * ldOut + col) =
                        __halves2half2(__float2half_rn(v0), __float2half_rn(v1));
                } else {
                    *reinterpret_cast<float2*>(OutF + (size_t)row * ldOut + col) = make_float2(v0, v1);
                }
            }
        }
    }
}

// ---------------- soft assignment (V=1 -> q = 1/(1+d2), row-normalized) ----
__global__ __launch_bounds__(256)
void soft_assign_kernel(const float* __restrict__ Z,
                        const float* __restrict__ clusters,
                        float* __restrict__ Q)
{
    __shared__ float sCl[K_CL][H1 + 1];
    const int tid = threadIdx.x;
    for (int i = tid; i < K_CL * H1; i += blockDim.x)
        sCl[i / H1][i % H1] = clusters[i];
    __syncthreads();

    const int warpId = tid >> 5;
    const int lane = tid & 31;
    const int row = blockIdx.x * 8 + warpId;
    if (row >= N_ROWS) return;

    const float* z = Z + (size_t)row * H1;
    float d2 = 0.0f;
    if (lane < K_CL) {
        #pragma unroll 8
        for (int d = 0; d < H1; d++) {
            float diff = z[d] - sCl[lane][d];
            d2 = fmaf(diff, diff, d2);
        }
    }
    float q = (lane < K_CL) ? 1.0f / (1.0f + d2) : 0.0f;
    float s = q;
    #pragma unroll
    for (int off = 16; off > 0; off >>= 1)
        s += __shfl_xor_sync(0xFFFFFFFFu, s, off);
    if (lane < K_CL)
        Q[(size_t)row * K_CL + lane] = q / s;
}

// ---------------- launch ----------------
extern "C" void kernel_launch(void* const* d_in, const int* in_sizes, int n_in,
                              void* d_out, int out_size)
{
    const float* x        = (const float*)d_in[0];
    const float* W1       = (const float*)d_in[1];
    const float* b1       = (const float*)d_in[2];
    const float* W2       = (const float*)d_in[3];
    const float* b2       = (const float*)d_in[4];
    const float* clusters = (const float*)d_in[5];

    float* z_out = (float*)d_out;
    float* q_out = (float*)d_out + (size_t)N_ROWS * H1;

    __half *w1t, *hh, *w2t;
    cudaGetSymbolAddress((void**)&w1t, g_w1t);
    cudaGetSymbolAddress((void**)&hh,  g_hh);
    cudaGetSymbolAddress((void**)&w2t, g_w2t);

    cudaFuncSetAttribute((const void*)gemm_mma_kernel<0, true>,
                         cudaFuncAttributeMaxDynamicSharedMemorySize, GEMM_SMEM);
    cudaFuncSetAttribute((const void*)gemm_mma_kernel<1, false>,
                         cudaFuncAttributeMaxDynamicSharedMemorySize, GEMM_SMEM);

    // 1) weight transposes (x conversion is fused into GEMM1's producers)
    transpose_kernel<<<dim3(KPAD1 / 32, H0 / 32), dim3(32, 8)>>>(W1, w1t, D_IN, H0, KPAD1);
    transpose_kernel<<<dim3(H0 / 32, H1 / 32), dim3(32, 8)>>>(W2, w2t, H0, H1, H0);

    // 2) GEMM1: H = silu(x @ W1 + b1) -> fp16 (A = x fp32, converted in-flight)
    gemm_mma_kernel<0, true><<<dim3(H0 / 128, N_ROWS / 128), 320, GEMM_SMEM>>>(
        x, w1t, b1, hh, nullptr, D_IN, KPAD1, D_IN, KPAD1 / 64, H0);

    // 3) GEMM2: z = H @ W2 + b2 -> fp32 (A = hh fp16)
    gemm_mma_kernel<1, false><<<dim3(H1 / 128, N_ROWS / 128), 320, GEMM_SMEM>>>(
        hh, w2t, b2, nullptr, z_out, H0, H0, H0, H0 / 64, H1);

    // 4) soft assignment
    soft_assign_kernel<<<N_ROWS / 8, 256>>>(z_out, clusters, q_out);
}

// round 12
// speedup vs baseline: 1.5982x; 1.5982x over previous
#include <cuda_runtime.h>
#include <cuda_fp16.h>
#include <math.h>
#include <stdint.h>

#define N_ROWS 32768
#define D_IN   3000
#define KPAD1  3072
#define H0     1024
#define H1     256
#define K_CL   20

// ---------------- scratch (static device arrays; no allocs) ----------------
__device__ __align__(16) __half g_xh[(size_t)N_ROWS * KPAD1];
__device__ __align__(16) __half g_w1t[(size_t)H0 * KPAD1];
__device__ __align__(16) __half g_hh[(size_t)N_ROWS * H0];
__device__ __align__(16) __half g_w2t[(size_t)H1 * H0];

// ---------------- helpers ----------------
__device__ __forceinline__ uint32_t smem_u32(const void* p) {
    uint32_t a;
    asm("{ .reg .u64 t; cvta.to.shared.u64 t, %1; cvt.u32.u64 %0, t; }" : "=r"(a) : "l"(p));
    return a;
}
__device__ __forceinline__ void cp_async16(uint32_t s, const void* g) {
    asm volatile("cp.async.cg.shared.global [%0], [%1], 16;" :: "r"(s), "l"(g));
}
__device__ __forceinline__ void cp_commit() {
    asm volatile("cp.async.commit_group;" ::: "memory");
}
template <int N>
__device__ __forceinline__ void cp_wait() {
    asm volatile("cp.async.wait_group %0;" :: "n"(N) : "memory");
}
__device__ __forceinline__ void ldm_x4(uint32_t* r, uint32_t addr) {
    asm volatile("ldmatrix.sync.aligned.m8n8.x4.shared.b16 {%0,%1,%2,%3}, [%4];"
        : "=r"(r[0]), "=r"(r[1]), "=r"(r[2]), "=r"(r[3]) : "r"(addr));
}
__device__ __forceinline__ void mma_f16(float* c, const uint32_t* a, const uint32_t* b) {
    asm volatile(
        "mma.sync.aligned.m16n8k16.row.col.f32.f16.f16.f32 "
        "{%0,%1,%2,%3}, {%4,%5,%6,%7}, {%8,%9}, {%0,%1,%2,%3};"
        : "+f"(c[0]), "+f"(c[1]), "+f"(c[2]), "+f"(c[3])
        : "r"(a[0]), "r"(a[1]), "r"(a[2]), "r"(a[3]), "r"(b[0]), "r"(b[1]));
}

// ---------------- preprocess kernels ----------------
// x [N_ROWS, D_IN] fp32 -> xh [N_ROWS, KPAD1] fp16, wide vector streaming.
// D_IN = 3000 = 750 float4 exactly; cols 3000..3071 zero-filled.
#define CVT_U_PER_ROW (KPAD1 / 4)   // 768 float4-units per padded row
__global__ __launch_bounds__(256)
void convert_x_kernel(const float* __restrict__ x,
                      __half* __restrict__ xh)
{
    const int64_t total = (int64_t)N_ROWS * CVT_U_PER_ROW;
    const int64_t stride = (int64_t)gridDim.x * blockDim.x;
    for (int64_t u = (int64_t)blockIdx.x * blockDim.x + threadIdx.x;
         u < total; u += stride) {
        const int row = (int)(u >> 9) / (CVT_U_PER_ROW >> 9) ; // placeholder, replaced below
    }
}

// (clean implementation without div tricks)
__global__ __launch_bounds__(256)
void convert_x_kernel2(const float* __restrict__ x,
                       __half* __restrict__ xh)
{
    const int64_t total  = (int64_t)N_ROWS * CVT_U_PER_ROW;
    const int64_t stride = (int64_t)gridDim.x * blockDim.x;
    for (int64_t u = (int64_t)blockIdx.x * blockDim.x + threadIdx.x;
         u < total; u += stride) {
        const int row = (int)(u / CVT_U_PER_ROW);
        const int c4  = (int)(u - (int64_t)row * CVT_U_PER_ROW);   // 0..767
        __half2 h0, h1;
        if (c4 < D_IN / 4) {
            const float4 v = *reinterpret_cast<const float4*>(
                x + (size_t)row * D_IN + c4 * 4);
            h0 = __floats2half2_rn(v.x, v.y);
            h1 = __floats2half2_rn(v.z, v.w);
        } else {
            h0 = __halves2half2(__float2half_rn(0.f), __float2half_rn(0.f));
            h1 = h0;
        }
        uint2 o;
        o.x = *reinterpret_cast<uint32_t*>(&h0);
        o.y = *reinterpret_cast<uint32_t*>(&h1);
        *reinterpret_cast<uint2*>(xh + (size_t)row * KPAD1 + c4 * 4) = o;
    }
}

// W [K, N] fp32 -> Wt [N, Kpad] fp16 (transposed, zero-padded K)
__global__ __launch_bounds__(256)
void transpose_kernel(const float* __restrict__ W,
                      __half* __restrict__ T,
                      int K, int N, int Kpad)
{
    __shared__ float s[32][33];
    const int k0 = blockIdx.x * 32;
    const int n0 = blockIdx.y * 32;
    const int tx = threadIdx.x, ty = threadIdx.y;
    #pragma unroll
    for (int j = 0; j < 32; j += 8) {
        int k = k0 + ty + j;
        s[ty + j][tx] = (k < K) ? W[(size_t)k * N + n0 + tx] : 0.0f;
    }
    __syncthreads();
    #pragma unroll
    for (int j = 0; j < 32; j += 8) {
        int n = n0 + ty + j;
        int kk = k0 + tx;
        T[(size_t)n * Kpad + kk] = __float2half_rn(s[tx][ty + j]);
    }
}

// ---------------- HMMA single-pass fp16 GEMM (R7 config — best known) ----
// CTA tile 128x128, warp tile 64x32 (8 warps, 2x4), K-chunk 64 fp16.
// Stage: [A 16K][B 16K] = 32KB; 3-stage pipeline = 96KB -> 2 CTAs/SM.
#define TILE_A   16384
#define STAGE_B  32768
#define NSTAGE   3
#define GEMM_SMEM (NSTAGE * STAGE_B)   // 98304

// EPI=0: bias+SiLU -> fp16.  EPI=1: bias -> fp32.
template <int EPI>
__global__ __launch_bounds__(256, 2)
void gemm_mma_kernel(const __half* __restrict__ A,
                     const __half* __restrict__ B,
                     const float* __restrict__ bias,
                     __half* __restrict__ OutH,
                     float* __restrict__ OutF,
                     int Kpad, int NC, int ldOut)
{
    extern __shared__ char smem[];
    const uint32_t sbase = smem_u32(smem);
    const int tid  = threadIdx.x;
    const int wid  = tid >> 5;
    const int lane = tid & 31;
    const int mBase = blockIdx.y * 128;
    const int nBase = blockIdx.x * 128;
    const int warpM = (wid & 1) * 64;    // 0 / 64
    const int warpN = (wid >> 1) * 32;   // 0..96

    // ---- per-thread load geometry (constant across chunks) ----
    const int row_ld = tid >> 3;          // 0..31
    const int c16    = tid & 7;           // 16B column
    const uint32_t swB = (uint32_t)(row_ld * 128 + ((c16 * 16) ^ ((row_ld & 7) << 4)));
    const char* gA = (const char*)(A + (size_t)(mBase + row_ld) * Kpad) + c16 * 16;
    const char* gB = (const char*)(B + (size_t)(nBase + row_ld) * Kpad) + c16 * 16;
    const size_t itStride = (size_t)32 * Kpad * sizeof(__half);   // 32 rows down

    // ---- per-warp ldmatrix offsets, fully precomputed ----
    const int aRowIn = lane & 15;
    const int kHalf  = (lane >> 4) << 4;  // 0 / 16 bytes
    uint32_t offA[4][4], offB[2][4];
    #pragma unroll
    for (int mt = 0; mt < 4; mt++) {
        int row = warpM + mt * 16 + aRowIn;
        int xr = (row & 7) << 4;
        #pragma unroll
        for (int ks = 0; ks < 4; ks++)
            offA[mt][ks] = (uint32_t)(row * 128 + ((ks * 32 + kHalf) ^ xr));
    }
    #pragma unroll
    for (int nt2 = 0; nt2 < 2; nt2++) {
        int row = warpN + nt2 * 16 + aRowIn;
        int xr = (row & 7) << 4;
        #pragma unroll
        for (int ks = 0; ks < 4; ks++)
            offB[nt2][ks] = (uint32_t)(row * 128 + ((ks * 32 + kHalf) ^ xr));
    }

    float acc[4][4][4];
    #pragma unroll
    for (int i = 0; i < 4; i++)
        #pragma unroll
        for (int j = 0; j < 4; j++)
            #pragma unroll
            for (int k = 0; k < 4; k++)
                acc[i][j][k] = 0.0f;

    // ---- pipelined loads ----
    auto load_stage = [&](int stage) {
        const uint32_t st = sbase + stage * STAGE_B;
        #pragma unroll
        for (int it = 0; it < 4; it++)
            cp_async16(st + swB + it * 4096, gA + it * itStride);
        #pragma unroll
        for (int it = 0; it < 4; it++)
            cp_async16(st + TILE_A + swB + it * 4096, gB + it * itStride);
        gA += 128; gB += 128;   // next 64-element K chunk
        cp_commit();
    };

    load_stage(0);
    load_stage(1);

    int sCompute = 0, sLoad = 2;
    for (int c = 0; c < NC; c++) {
        if (c == NC - 1) cp_wait<0>(); else cp_wait<1>();
        __syncthreads();
        if (c + 2 < NC) {
            load_stage(sLoad);
            if (++sLoad == NSTAGE) sLoad = 0;
        }

        const uint32_t st = sbase + sCompute * STAGE_B;
        if (++sCompute == NSTAGE) sCompute = 0;

        #pragma unroll
        for (int ks = 0; ks < 4; ks++) {
            uint32_t fa[4][4], fb[4][2];
            #pragma unroll
            for (int mt = 0; mt < 4; mt++)
                ldm_x4(fa[mt], st + offA[mt][ks]);
            #pragma unroll
            for (int nt2 = 0; nt2 < 2; nt2++) {
                uint32_t r[4];
                ldm_x4(r, st + TILE_A + offB[nt2][ks]);
                fb[nt2 * 2][0] = r[0]; fb[nt2 * 2][1] = r[2];
                fb[nt2 * 2 + 1][0] = r[1]; fb[nt2 * 2 + 1][1] = r[3];
            }
            #pragma unroll
            for (int mt = 0; mt < 4; mt++)
                #pragma unroll
                for (int nt = 0; nt < 4; nt++)
                    mma_f16(acc[mt][nt], fa[mt], fb[nt]);
        }
    }

    // ---- epilogue ----
    const int rBase = mBase + warpM + (lane >> 2);
    const int cBase = nBase + warpN + (lane & 3) * 2;

    #pragma unroll
    for (int mt = 0; mt < 4; mt++) {
        #pragma unroll
        for (int nt = 0; nt < 4; nt++) {
            const int col = cBase + nt * 8;
            const float b0 = bias[col];
            const float b1 = bias[col + 1];
            #pragma unroll
            for (int h = 0; h < 2; h++) {
                const int row = rBase + mt * 16 + h * 8;
                float v0 = acc[mt][nt][2 * h]     + b0;
                float v1 = acc[mt][nt][2 * h + 1] + b1;
                if (EPI == 0) {
                    v0 = v0 / (1.0f + expf(-v0));
                    v1 = v1 / (1.0f + expf(-v1));
                    *reinterpret_cast<__half2*>(OutH + (size_t)row * ldOut + col) =
                        __halves2half2(__float2half_rn(v0), __float2half_rn(v1));
                } else {
                    *reinterpret_cast<float2*>(OutF + (size_t)row * ldOut + col) = make_float2(v0, v1);
                }
            }
        }
    }
}

// ---------------- soft assignment (V=1 -> q = 1/(1+d2), row-normalized) ----
__global__ __launch_bounds__(256)
void soft_assign_kernel(const float* __restrict__ Z,
                        const float* __restrict__ clusters,
                        float* __restrict__ Q)
{
    __shared__ float sCl[K_CL][H1 + 1];
    const int tid = threadIdx.x;
    for (int i = tid; i < K_CL * H1; i += blockDim.x)
        sCl[i / H1][i % H1] = clusters[i];
    __syncthreads();

    const int warpId = tid >> 5;
    const int lane = tid & 31;
    const int row = blockIdx.x * 8 + warpId;
    if (row >= N_ROWS) return;

    const float* z = Z + (size_t)row * H1;
    float d2 = 0.0f;
    if (lane < K_CL) {
        #pragma unroll 8
        for (int d = 0; d < H1; d++) {
            float diff = z[d] - sCl[lane][d];
            d2 = fmaf(diff, diff, d2);
        }
    }
    float q = (lane < K_CL) ? 1.0f / (1.0f + d2) : 0.0f;
    float s = q;
    #pragma unroll
    for (int off = 16; off > 0; off >>= 1)
        s += __shfl_xor_sync(0xFFFFFFFFu, s, off);
    if (lane < K_CL)
        Q[(size_t)row * K_CL + lane] = q / s;
}

// ---------------- launch ----------------
extern "C" void kernel_launch(void* const* d_in, const int* in_sizes, int n_in,
                              void* d_out, int out_size)
{
    const float* x        = (const float*)d_in[0];
    const float* W1       = (const float*)d_in[1];
    const float* b1       = (const float*)d_in[2];
    const float* W2       = (const float*)d_in[3];
    const float* b2       = (const float*)d_in[4];
    const float* clusters = (const float*)d_in[5];

    float* z_out = (float*)d_out;
    float* q_out = (float*)d_out + (size_t)N_ROWS * H1;

    __half *xh, *w1t, *hh, *w2t;
    cudaGetSymbolAddress((void**)&xh,  g_xh);
    cudaGetSymbolAddress((void**)&w1t, g_w1t);
    cudaGetSymbolAddress((void**)&hh,  g_hh);
    cudaGetSymbolAddress((void**)&w2t, g_w2t);

    cudaFuncSetAttribute(gemm_mma_kernel<0>, cudaFuncAttributeMaxDynamicSharedMemorySize, GEMM_SMEM);
    cudaFuncSetAttribute(gemm_mma_kernel<1>, cudaFuncAttributeMaxDynamicSharedMemorySize, GEMM_SMEM);

    // 1) convert inputs to fp16 (wide streaming) + weight transposes
    convert_x_kernel2<<<2048, 256>>>(x, xh);
    transpose_kernel<<<dim3(KPAD1 / 32, H0 / 32), dim3(32, 8)>>>(W1, w1t, D_IN, H0, KPAD1);
    transpose_kernel<<<dim3(H0 / 32, H1 / 32), dim3(32, 8)>>>(W2, w2t, H0, H1, H0);

    // 2) GEMM1: H = silu(x @ W1 + b1) -> fp16
    gemm_mma_kernel<0><<<dim3(H0 / 128, N_ROWS / 128), 256, GEMM_SMEM>>>(
        xh, w1t, b1, hh, nullptr, KPAD1, KPAD1 / 64, H0);

    // 3) GEMM2: z = H @ W2 + b2 -> fp32
    gemm_mma_kernel<1><<<dim3(H1 / 128, N_ROWS / 128), 256, GEMM_SMEM>>>(
        hh, w2t, b2, nullptr, z_out, H0, H0 / 64, H1);

    // 4) soft assignment
    soft_assign_kernel<<<N_ROWS / 8, 256>>>(z_out, clusters, q_out);
}

// round 13
// speedup vs baseline: 1.6406x; 1.0265x over previous
#include <cuda_runtime.h>
#include <cuda_fp16.h>
#include <math.h>
#include <stdint.h>

#define N_ROWS 32768
#define D_IN   3000
#define KPAD1  3072
#define H0     1024
#define H1     256
#define K_CL   20

// ---------------- scratch (static device arrays; no allocs) ----------------
__device__ __align__(16) __half g_xh[(size_t)N_ROWS * KPAD1];
__device__ __align__(16) __half g_w1t[(size_t)H0 * KPAD1];
__device__ __align__(16) __half g_hh[(size_t)N_ROWS * H0];
__device__ __align__(16) __half g_w2t[(size_t)H1 * H0];

// ---------------- helpers ----------------
__device__ __forceinline__ uint32_t smem_u32(const void* p) {
    uint32_t a;
    asm("{ .reg .u64 t; cvta.to.shared.u64 t, %1; cvt.u32.u64 %0, t; }" : "=r"(a) : "l"(p));
    return a;
}
__device__ __forceinline__ void cp_async16(uint32_t s, const void* g) {
    asm volatile("cp.async.cg.shared.global [%0], [%1], 16;" :: "r"(s), "l"(g));
}
__device__ __forceinline__ void cp_commit() {
    asm volatile("cp.async.commit_group;" ::: "memory");
}
template <int N>
__device__ __forceinline__ void cp_wait() {
    asm volatile("cp.async.wait_group %0;" :: "n"(N) : "memory");
}
__device__ __forceinline__ void ldm_x4(uint32_t* r, uint32_t addr) {
    asm volatile("ldmatrix.sync.aligned.m8n8.x4.shared.b16 {%0,%1,%2,%3}, [%4];"
        : "=r"(r[0]), "=r"(r[1]), "=r"(r[2]), "=r"(r[3]) : "r"(addr));
}
__device__ __forceinline__ void mma_f16(float* c, const uint32_t* a, const uint32_t* b) {
    asm volatile(
        "mma.sync.aligned.m16n8k16.row.col.f32.f16.f16.f32 "
        "{%0,%1,%2,%3}, {%4,%5,%6,%7}, {%8,%9}, {%0,%1,%2,%3};"
        : "+f"(c[0]), "+f"(c[1]), "+f"(c[2]), "+f"(c[3])
        : "r"(a[0]), "r"(a[1]), "r"(a[2]), "r"(a[3]), "r"(b[0]), "r"(b[1]));
}

// ---------------- preprocess kernels ----------------
// x [N_ROWS, D_IN] fp32 -> xh [N_ROWS, KPAD1] fp16, wide vector streaming.
// D_IN = 3000 = 750 float4 exactly; cols 3000..3071 zero-filled.
#define CVT_U_PER_ROW (KPAD1 / 4)   // 768 float4-units per padded row
__global__ __launch_bounds__(256)
void convert_x_kernel(const float* __restrict__ x,
                      __half* __restrict__ xh)
{
    const int64_t total  = (int64_t)N_ROWS * CVT_U_PER_ROW;
    const int64_t stride = (int64_t)gridDim.x * blockDim.x;
    for (int64_t u = (int64_t)blockIdx.x * blockDim.x + threadIdx.x;
         u < total; u += stride) {
        const int row = (int)(u / CVT_U_PER_ROW);
        const int c4  = (int)(u - (int64_t)row * CVT_U_PER_ROW);   // 0..767
        __half2 h0, h1;
        if (c4 < D_IN / 4) {
            const float4 v = *reinterpret_cast<const float4*>(
                x + (size_t)row * D_IN + c4 * 4);
            h0 = __floats2half2_rn(v.x, v.y);
            h1 = __floats2half2_rn(v.z, v.w);
        } else {
            h0 = __halves2half2(__float2half_rn(0.f), __float2half_rn(0.f));
            h1 = h0;
        }
        uint2 o;
        o.x = *reinterpret_cast<uint32_t*>(&h0);
        o.y = *reinterpret_cast<uint32_t*>(&h1);
        *reinterpret_cast<uint2*>(xh + (size_t)row * KPAD1 + c4 * 4) = o;
    }
}

// W [K, N] fp32 -> Wt [N, Kpad] fp16 (transposed, zero-padded K)
__global__ __launch_bounds__(256)
void transpose_kernel(const float* __restrict__ W,
                      __half* __restrict__ T,
                      int K, int N, int Kpad)
{
    __shared__ float s[32][33];
    const int k0 = blockIdx.x * 32;
    const int n0 = blockIdx.y * 32;
    const int tx = threadIdx.x, ty = threadIdx.y;
    #pragma unroll
    for (int j = 0; j < 32; j += 8) {
        int k = k0 + ty + j;
        s[ty + j][tx] = (k < K) ? W[(size_t)k * N + n0 + tx] : 0.0f;
    }
    __syncthreads();
    #pragma unroll
    for (int j = 0; j < 32; j += 8) {
        int n = n0 + ty + j;
        int kk = k0 + tx;
        T[(size_t)n * Kpad + kk] = __float2half_rn(s[tx][ty + j]);
    }
}

// ---------------- HMMA single-pass fp16 GEMM ----------------
// CTA tile 128x128, warp tile 64x32 (8 warps, 2x4), K-chunk 64 fp16.
// Stage: [A 16K][B 16K] = 32KB; 3-stage pipeline = 96KB -> 2 CTAs/SM.
// cp.async for the next stage is issued in QUARTERS, one per ks-step,
// between that step's LDSM group and its MMA group, to avoid the
// post-barrier LSU convoy that starves the tensor pipe.
#define TILE_A   16384
#define STAGE_B  32768
#define NSTAGE   3
#define GEMM_SMEM (NSTAGE * STAGE_B)   // 98304

// EPI=0: bias+SiLU -> fp16.  EPI=1: bias -> fp32.
template <int EPI>
__global__ __launch_bounds__(256, 2)
void gemm_mma_kernel(const __half* __restrict__ A,
                     const __half* __restrict__ B,
                     const float* __restrict__ bias,
                     __half* __restrict__ OutH,
                     float* __restrict__ OutF,
                     int Kpad, int NC, int ldOut)
{
    extern __shared__ char smem[];
    const uint32_t sbase = smem_u32(smem);
    const int tid  = threadIdx.x;
    const int wid  = tid >> 5;
    const int lane = tid & 31;
    const int mBase = blockIdx.y * 128;
    const int nBase = blockIdx.x * 128;
    const int warpM = (wid & 1) * 64;    // 0 / 64
    const int warpN = (wid >> 1) * 32;   // 0..96

    // ---- per-thread load geometry (constant across chunks) ----
    const int row_ld = tid >> 3;          // 0..31
    const int c16    = tid & 7;           // 16B column
    const uint32_t swB = (uint32_t)(row_ld * 128 + ((c16 * 16) ^ ((row_ld & 7) << 4)));
    const char* gA = (const char*)(A + (size_t)(mBase + row_ld) * Kpad) + c16 * 16;
    const char* gB = (const char*)(B + (size_t)(nBase + row_ld) * Kpad) + c16 * 16;
    const size_t itStride = (size_t)32 * Kpad * sizeof(__half);   // 32 rows down

    // ---- per-warp ldmatrix offsets, fully precomputed ----
    const int aRowIn = lane & 15;
    const int kHalf  = (lane >> 4) << 4;  // 0 / 16 bytes
    uint32_t offA[4][4], offB[2][4];
    #pragma unroll
    for (int mt = 0; mt < 4; mt++) {
        int row = warpM + mt * 16 + aRowIn;
        int xr = (row & 7) << 4;
        #pragma unroll
        for (int ks = 0; ks < 4; ks++)
            offA[mt][ks] = (uint32_t)(row * 128 + ((ks * 32 + kHalf) ^ xr));
    }
    #pragma unroll
    for (int nt2 = 0; nt2 < 2; nt2++) {
        int row = warpN + nt2 * 16 + aRowIn;
        int xr = (row & 7) << 4;
        #pragma unroll
        for (int ks = 0; ks < 4; ks++)
            offB[nt2][ks] = (uint32_t)(row * 128 + ((ks * 32 + kHalf) ^ xr));
    }

    float acc[4][4][4];
    #pragma unroll
    for (int i = 0; i < 4; i++)
        #pragma unroll
        for (int j = 0; j < 4; j++)
            #pragma unroll
            for (int k = 0; k < 4; k++)
                acc[i][j][k] = 0.0f;

    // ---- full-stage load (used only for the 2-stage prologue) ----
    auto load_stage = [&](int stage) {
        const uint32_t st = sbase + stage * STAGE_B;
        #pragma unroll
        for (int it = 0; it < 4; it++)
            cp_async16(st + swB + it * 4096, gA + it * itStride);
        #pragma unroll
        for (int it = 0; it < 4; it++)
            cp_async16(st + TILE_A + swB + it * 4096, gB + it * itStride);
        gA += 128; gB += 128;
        cp_commit();
    };
    // ---- quarter-stage load: 2 cp.async per thread ----
    auto load_part = [&](int stage, int part) {
        const uint32_t st = sbase + stage * STAGE_B;
        cp_async16(st + swB + part * 4096, gA + part * itStride);
        cp_async16(st + TILE_A + swB + part * 4096, gB + part * itStride);
    };

    load_stage(0);
    load_stage(1);

    int sCompute = 0, sLoad = 2;
    for (int c = 0; c < NC; c++) {
        if (c == NC - 1) cp_wait<0>(); else cp_wait<1>();
        __syncthreads();

        const bool doLoad = (c + 2 < NC);
        const uint32_t st = sbase + sCompute * STAGE_B;
        if (++sCompute == NSTAGE) sCompute = 0;

        #pragma unroll
        for (int ks = 0; ks < 4; ks++) {
            uint32_t fa[4][4], fb[4][2];
            #pragma unroll
            for (int mt = 0; mt < 4; mt++)
                ldm_x4(fa[mt], st + offA[mt][ks]);
            #pragma unroll
            for (int nt2 = 0; nt2 < 2; nt2++) {
                uint32_t r[4];
                ldm_x4(r, st + TILE_A + offB[nt2][ks]);
                fb[nt2 * 2][0] = r[0]; fb[nt2 * 2][1] = r[2];
                fb[nt2 * 2 + 1][0] = r[1]; fb[nt2 * 2 + 1][1] = r[3];
            }
            // issue next-stage quarter between LDSM and MMA (fills LDSM latency,
            // keeps LSU busy without a post-barrier convoy)
            if (doLoad) load_part(sLoad, ks);
            #pragma unroll
            for (int mt = 0; mt < 4; mt++)
                #pragma unroll
                for (int nt = 0; nt < 4; nt++)
                    mma_f16(acc[mt][nt], fa[mt], fb[nt]);
        }
        if (doLoad) {
            gA += 128; gB += 128;
            cp_commit();
            if (++sLoad == NSTAGE) sLoad = 0;
        }
    }

    // ---- epilogue ----
    const int rBase = mBase + warpM + (lane >> 2);
    const int cBase = nBase + warpN + (lane & 3) * 2;

    #pragma unroll
    for (int mt = 0; mt < 4; mt++) {
        #pragma unroll
        for (int nt = 0; nt < 4; nt++) {
            const int col = cBase + nt * 8;
            const float b0 = bias[col];
            const float b1 = bias[col + 1];
            #pragma unroll
            for (int h = 0; h < 2; h++) {
                const int row = rBase + mt * 16 + h * 8;
                float v0 = acc[mt][nt][2 * h]     + b0;
                float v1 = acc[mt][nt][2 * h + 1] + b1;
                if (EPI == 0) {
                    v0 = v0 / (1.0f + expf(-v0));
                    v1 = v1 / (1.0f + expf(-v1));
                    *reinterpret_cast<__half2*>(OutH + (size_t)row * ldOut + col) =
                        __halves2half2(__float2half_rn(v0), __float2half_rn(v1));
                } else {
                    *reinterpret_cast<float2*>(OutF + (size_t)row * ldOut + col) = make_float2(v0, v1);
                }
            }
        }
    }
}

// ---------------- soft assignment (V=1 -> q = 1/(1+d2), row-normalized) ----
__global__ __launch_bounds__(256)
void soft_assign_kernel(const float* __restrict__ Z,
                        const float* __restrict__ clusters,
                        float* __restrict__ Q)
{
    __shared__ float sCl[K_CL][H1 + 1];
    const int tid = threadIdx.x;
    for (int i = tid; i < K_CL * H1; i += blockDim.x)
        sCl[i / H1][i % H1] = clusters[i];
    __syncthreads();

    const int warpId = tid >> 5;
    const int lane = tid & 31;
    const int row = blockIdx.x * 8 + warpId;
    if (row >= N_ROWS) return;

    const float* z = Z + (size_t)row * H1;
    float d2 = 0.0f;
    if (lane < K_CL) {
        #pragma unroll 8
        for (int d = 0; d < H1; d++) {
            float diff = z[d] - sCl[lane][d];
            d2 = fmaf(diff, diff, d2);
        }
    }
    float q = (lane < K_CL) ? 1.0f / (1.0f + d2) : 0.0f;
    float s = q;
    #pragma unroll
    for (int off = 16; off > 0; off >>= 1)
        s += __shfl_xor_sync(0xFFFFFFFFu, s, off);
    if (lane < K_CL)
        Q[(size_t)row * K_CL + lane] = q / s;
}

// ---------------- launch ----------------
extern "C" void kernel_launch(void* const* d_in, const int* in_sizes, int n_in,
                              void* d_out, int out_size)
{
    const float* x        = (const float*)d_in[0];
    const float* W1       = (const float*)d_in[1];
    const float* b1       = (const float*)d_in[2];
    const float* W2       = (const float*)d_in[3];
    const float* b2       = (const float*)d_in[4];
    const float* clusters = (const float*)d_in[5];

    float* z_out = (float*)d_out;
    float* q_out = (float*)d_out + (size_t)N_ROWS * H1;

    __half *xh, *w1t, *hh, *w2t;
    cudaGetSymbolAddress((void**)&xh,  g_xh);
    cudaGetSymbolAddress((void**)&w1t, g_w1t);
    cudaGetSymbolAddress((void**)&hh,  g_hh);
    cudaGetSymbolAddress((void**)&w2t, g_w2t);

    cudaFuncSetAttribute(gemm_mma_kernel<0>, cudaFuncAttributeMaxDynamicSharedMemorySize, GEMM_SMEM);
    cudaFuncSetAttribute(gemm_mma_kernel<1>, cudaFuncAttributeMaxDynamicSharedMemorySize, GEMM_SMEM);

    // 1) convert inputs to fp16 (wide streaming) + weight transposes
    convert_x_kernel<<<2048, 256>>>(x, xh);
    transpose_kernel<<<dim3(KPAD1 / 32, H0 / 32), dim3(32, 8)>>>(W1, w1t, D_IN, H0, KPAD1);
    transpose_kernel<<<dim3(H0 / 32, H1 / 32), dim3(32, 8)>>>(W2, w2t, H0, H1, H0);

    // 2) GEMM1: H = silu(x @ W1 + b1) -> fp16
    gemm_mma_kernel<0><<<dim3(H0 / 128, N_ROWS / 128), 256, GEMM_SMEM>>>(
        xh, w1t, b1, hh, nullptr, KPAD1, KPAD1 / 64, H0);

    // 3) GEMM2: z = H @ W2 + b2 -> fp32
    gemm_mma_kernel<1><<<dim3(H1 / 128, N_ROWS / 128), 256, GEMM_SMEM>>>(
        hh, w2t, b2, nullptr, z_out, H0, H0 / 64, H1);

    // 4) soft assignment
    soft_assign_kernel<<<N_ROWS / 8, 256>>>(z_out, clusters, q_out);
}